// round 16
// baseline (speedup 1.0000x reference)
#include <cuda_runtime.h>

// Shapes fixed by the reference
#define NB   4
#define DB   8
#define CB   3
#define RB   4
#define KK   5
#define HH   128
#define WW   128
#define HWSZ (HH * WW)
#define TW   32                     // tile width
#define TH   4                      // tile height
#define SH_  (TH + 4)               // 8
#define SW_  (TW + 4)               // 36

// ld.global.nc with 256B L2 prefetch: each miss fetches the full 256B sector
// pair, so the horizontally-adjacent co-resident block hits in L2 and the
// memory controller sees 256B-granular, row-friendly traffic.
__device__ __forceinline__ float ldg_nc_256(const float* p) {
    float v;
    asm volatile("ld.global.nc.L2::256B.f32 %0, [%1];" : "=f"(v) : "l"(p));
    return v;
}

// Block: x=32 (pixel col), y=2 (si group), z=4 (rows). 256 threads, 8 CTAs/SM.
// Thread: 1 pixel x 1 si-group (r = 2si, 2si+1) x 3 channels = 6 accumulators.
__global__ __launch_bounds__(256, 8)
void adaptive_conv_ps_v14(const float* __restrict__ burst,
                          const float* __restrict__ kernels,
                          float* __restrict__ out)
{
    __shared__ float s[CB][SH_][SW_];

    const int nd = blockIdx.z;                 // 0..31
    const int h0 = blockIdx.y * TH;
    const int w0 = blockIdx.x * TW;
    const int tx = threadIdx.x;                // 0..31
    const int si = threadIdx.y;                // 0..1
    const int tz = threadIdx.z;                // 0..3
    const int tid = (tz * 2 + si) * 32 + tx;

    // ---- stage burst tile (3 ch, halo 2, zero-pad OOB): 864 elems ----
    const float* bptr = burst + (size_t)nd * CB * HWSZ;
    #pragma unroll
    for (int k = 0; k < 4; k++) {
        int idx = tid + k * 256;
        if (idx < CB * SH_ * SW_) {
            int c   = idx / (SH_ * SW_);
            int rem = idx - c * (SH_ * SW_);
            int sh  = rem / SW_;
            int sw  = rem - sh * SW_;
            int gh  = h0 + sh - 2;
            int gw  = w0 + sw - 2;
            float v = 0.0f;
            if (gh >= 0 && gh < HH && gw >= 0 && gw < WW)
                v = bptr[c * HWSZ + gh * WW + gw];
            s[c][sh][sw] = v;
        }
    }
    __syncthreads();

    const int h = h0 + tz;
    const int w = w0 + tx;

    float a00 = 0.f, a01 = 0.f;   // acc[c][sj]
    float a10 = 0.f, a11 = 0.f;
    float a20 = 0.f, a21 = 0.f;

    // kernels: (nd, r, i, j, h, w). This thread reads r = 2*si (k0) and 2*si+1 (k1).
    const float* kp = kernels
                    + ((size_t)nd * (RB * KK * KK) + (size_t)si * (2 * KK * KK)) * HWSZ
                    + (size_t)h * WW + w;

    #pragma unroll
    for (int i = 0; i < KK; i++) {
        #pragma unroll
        for (int j = 0; j < KK; j++) {
            const int t = i * KK + j;
            const float k0 = ldg_nc_256(kp + (size_t)t * HWSZ);
            const float k1 = ldg_nc_256(kp + (size_t)(t + KK * KK) * HWSZ);
            const float b0 = s[0][tz + i][tx + j];
            const float b1 = s[1][tz + i][tx + j];
            const float b2 = s[2][tz + i][tx + j];
            a00 = fmaf(k0, b0, a00);  a01 = fmaf(k1, b0, a01);
            a10 = fmaf(k0, b1, a10);  a11 = fmaf(k1, b1, a11);
            a20 = fmaf(k0, b2, a20);  a21 = fmaf(k1, b2, a21);
        }
    }

    // ---- fused pixel shuffle: out (nd, c, 2H, 2W); row 2h+si, cols 2w..2w+1 ----
    float2* o2 = reinterpret_cast<float2*>(out);
    const size_t rowbase = ((size_t)nd * CB) * (2 * HH) + (2 * h + si);
    __stcs(&o2[(rowbase + 0 * 2 * HH) * WW + w], make_float2(a00, a01));
    __stcs(&o2[(rowbase + 1 * 2 * HH) * WW + w], make_float2(a10, a11));
    __stcs(&o2[(rowbase + 2 * 2 * HH) * WW + w], make_float2(a20, a21));
}

extern "C" void kernel_launch(void* const* d_in, const int* in_sizes, int n_in,
                              void* d_out, int out_size)
{
    const float* burst   = (const float*)d_in[0];   // (4,8,3,128,128)
    const float* kernels = (const float*)d_in[1];   // (4,8,4,5,5,128,128)
    float* out = (float*)d_out;                     // (4,8,3,256,256)

    dim3 block(32, 2, 4);                           // 256 threads
    dim3 grid(WW / TW, HH / TH, NB * DB);           // (4, 32, 32) = 4096 blocks
    adaptive_conv_ps_v14<<<grid, block>>>(burst, kernels, out);
}

// round 17
// speedup vs baseline: 1.0499x; 1.0499x over previous
#include <cuda_runtime.h>

// Shapes fixed by the reference
#define NB   4
#define DB   8
#define CB   3
#define RB   4
#define KK   5
#define HH   128
#define WW   128
#define HWSZ (HH * WW)
#define TW   32                     // tile width
#define TH   8                      // tile height (doubled vs v4: halves halo traffic)
#define SH_  (TH + 4)               // 12
#define SW_  (TW + 4)               // 36
#define TILE_FLOATS (CB * SH_ * SW_)   // 1296

// Block: x=32 (pixel col), y=2 (si group), z=8 (rows). 512 threads, 4 CTAs/SM
// (2048 thr/SM, identical residency and per-thread datapath to v4).
__global__ __launch_bounds__(512, 4)
void adaptive_conv_ps_v15(const float* __restrict__ burst,
                          const float* __restrict__ kernels,
                          float* __restrict__ out)
{
    __shared__ float s[CB][SH_][SW_];

    const int nd = blockIdx.z;                 // 0..31
    const int h0 = blockIdx.y * TH;
    const int w0 = blockIdx.x * TW;
    const int tx = threadIdx.x;                // 0..31
    const int si = threadIdx.y;                // 0..1
    const int tz = threadIdx.z;                // 0..7
    const int tid = (tz * 2 + si) * 32 + tx;

    // ---- stage burst tile (3 ch, halo 2, zero-pad OOB): 1296 elems ----
    const float* bptr = burst + (size_t)nd * CB * HWSZ;
    #pragma unroll
    for (int k = 0; k < 3; k++) {
        int idx = tid + k * 512;
        if (idx < TILE_FLOATS) {
            int c   = idx / (SH_ * SW_);
            int rem = idx - c * (SH_ * SW_);
            int sh  = rem / SW_;
            int sw  = rem - sh * SW_;
            int gh  = h0 + sh - 2;
            int gw  = w0 + sw - 2;
            float v = 0.0f;
            if (gh >= 0 && gh < HH && gw >= 0 && gw < WW)
                v = bptr[c * HWSZ + gh * WW + gw];
            s[c][sh][sw] = v;
        }
    }
    __syncthreads();

    const int h = h0 + tz;
    const int w = w0 + tx;

    float a00 = 0.f, a01 = 0.f;   // acc[c][sj]
    float a10 = 0.f, a11 = 0.f;
    float a20 = 0.f, a21 = 0.f;

    // kernels: (nd, r, i, j, h, w). This thread reads r = 2*si (k0) and 2*si+1 (k1).
    const float* kp = kernels
                    + ((size_t)nd * (RB * KK * KK) + (size_t)si * (2 * KK * KK)) * HWSZ
                    + (size_t)h * WW + w;

    #pragma unroll
    for (int i = 0; i < KK; i++) {
        #pragma unroll
        for (int j = 0; j < KK; j++) {
            const int t = i * KK + j;
            const float k0 = __ldcs(kp + (size_t)t * HWSZ);
            const float k1 = __ldcs(kp + (size_t)(t + KK * KK) * HWSZ);
            const float b0 = s[0][tz + i][tx + j];
            const float b1 = s[1][tz + i][tx + j];
            const float b2 = s[2][tz + i][tx + j];
            a00 = fmaf(k0, b0, a00);  a01 = fmaf(k1, b0, a01);
            a10 = fmaf(k0, b1, a10);  a11 = fmaf(k1, b1, a11);
            a20 = fmaf(k0, b2, a20);  a21 = fmaf(k1, b2, a21);
        }
    }

    // ---- fused pixel shuffle: out (nd, c, 2H, 2W); row 2h+si, cols 2w..2w+1 ----
    float2* o2 = reinterpret_cast<float2*>(out);
    const size_t rowbase = ((size_t)nd * CB) * (2 * HH) + (2 * h + si);
    __stcs(&o2[(rowbase + 0 * 2 * HH) * WW + w], make_float2(a00, a01));
    __stcs(&o2[(rowbase + 1 * 2 * HH) * WW + w], make_float2(a10, a11));
    __stcs(&o2[(rowbase + 2 * 2 * HH) * WW + w], make_float2(a20, a21));
}

extern "C" void kernel_launch(void* const* d_in, const int* in_sizes, int n_in,
                              void* d_out, int out_size)
{
    const float* burst   = (const float*)d_in[0];   // (4,8,3,128,128)
    const float* kernels = (const float*)d_in[1];   // (4,8,4,5,5,128,128)
    float* out = (float*)d_out;                     // (4,8,3,256,256)

    dim3 block(32, 2, 8);                           // 512 threads
    dim3 grid(WW / TW, HH / TH, NB * DB);           // (4, 16, 32) = 2048 blocks
    adaptive_conv_ps_v15<<<grid, block>>>(burst, kernels, out);
}